// round 15
// baseline (speedup 1.0000x reference)
#include <cuda_runtime.h>

#define HH 512
#define WW 512
#define BB 2
#define NP 256          // uint32 pixel-pairs per row
#define PINF 1e12f

// Packed row-pass result, one uint16 per pixel:
//   bit15 = mask (1 = fg), bits[0:15) = row distance to nearest OPPOSITE-class
//   pixel (0x7fff sentinel = none in this row; its squared value ~1.07e9 can
//   never beat any real candidate). 1 MB, L2-resident.
__device__ unsigned short g_pack16[BB * HH * WW];

// ---------------------------------------------------------------------------
// Kernel A: row pass, 4 pixels/thread via float4 (fastest measured variant,
// R13). 4 rows per block (512 thr = 4 x 128). Row bitmask built with
// shfl_xor nibble packing; nearest-opposite-bit via ffs/clz word scans.
// ---------------------------------------------------------------------------
__global__ void __launch_bounds__(512) row_pass(const float* __restrict__ gt) {
    const int g = blockIdx.x * 4 + (threadIdx.x >> 7);   // global row id
    const int tx = threadIdx.x & 127;                    // float4 index in row
    const int rl = threadIdx.x >> 7;

    __shared__ unsigned int sw[4][WW / 32];

    const float4 v = reinterpret_cast<const float4*>(gt + (size_t)g * WW)[tx];
    const unsigned int nib = ((v.x == 1.0f) ? 1u : 0u)
                           | ((v.y == 1.0f) ? 2u : 0u)
                           | ((v.z == 1.0f) ? 4u : 0u)
                           | ((v.w == 1.0f) ? 8u : 0u);

    unsigned int pv = nib << (4 * (tx & 7));
    pv |= __shfl_xor_sync(0xFFFFFFFFu, pv, 1);
    pv |= __shfl_xor_sync(0xFFFFFFFFu, pv, 2);
    pv |= __shfl_xor_sync(0xFFFFFFFFu, pv, 4);
    if ((tx & 7) == 0) sw[rl][tx >> 3] = pv;
    __syncthreads();

    const int w0 = tx >> 3;                    // all 4 px share this word
    unsigned long long res = 0ull;

    #pragma unroll
    for (int k = 0; k < 4; ++k) {
        const int x = tx * 4 + k;
        const unsigned int m = (nib >> k) & 1u;
        const unsigned int xorm = m ? 0xFFFFFFFFu : 0u;
        const int off = x & 31;
        const unsigned int cur = sw[rl][w0] ^ xorm;

        int right = 0x7fff;
        {
            const unsigned int hi = cur & (0xFFFFFFFEu << off);
            if (hi) {
                right = (__ffs(hi) - 1) - off;
            } else {
                #pragma unroll 1
                for (int w = w0 + 1; w < WW / 32; ++w) {
                    const unsigned int q = sw[rl][w] ^ xorm;
                    if (q) { right = (w << 5) + (__ffs(q) - 1) - x; break; }
                }
            }
        }
        int left = 0x7fff;
        {
            const unsigned int lo = cur & ((1u << off) - 1u);
            if (lo) {
                left = off - (31 - __clz(lo));
            } else {
                #pragma unroll 1
                for (int w = w0 - 1; w >= 0; --w) {
                    const unsigned int q = sw[rl][w] ^ xorm;
                    if (q) { left = x - ((w << 5) + (31 - __clz(q))); break; }
                }
            }
        }

        const unsigned int d = (unsigned int)min(min(left, right), 0x7fff);
        res |= (unsigned long long)(d | (m << 15)) << (16 * k);
    }

    reinterpret_cast<unsigned long long*>(g_pack16 + (size_t)g * WW)[tx] = res;
}

// Branchless fold of one neighbor word into the running mins.
__device__ __forceinline__ void fold(unsigned int q, unsigned int mA,
                                     unsigned int mB, float pen,
                                     float& bestA, float& bestB) {
    const int ra = (int)(q & 0x7fffu);
    const int rb = (int)((q >> 16) & 0x7fffu);
    const float fa = (((q >> 15) & 1u) != mA) ? 0.0f : (float)(ra * ra);
    const float fb = (((q >> 31) & 1u) != mB) ? 0.0f : (float)(rb * rb);
    bestA = fminf(bestA, fa + pen);
    bestB = fminf(bestB, fb + pen);
}

// One independent-load chunk of radii [rlo, rlo+N): 2N clamped loads issued
// back-to-back (single L2 round-trip), folded branchlessly.
template <int N>
__device__ __forceinline__ void chunk(const unsigned int* __restrict__ col,
                                      int i, int rlo, unsigned int mA,
                                      unsigned int mB, float& bestA,
                                      float& bestB) {
    unsigned int qu[N], qd[N];
    #pragma unroll
    for (int k = 0; k < N; ++k) {
        const int r = rlo + k;
        qu[k] = col[max(i - r, 0) * NP];
        qd[k] = col[min(i + r, HH - 1) * NP];
    }
    #pragma unroll
    for (int k = 0; k < N; ++k) {
        const int r = rlo + k;
        const float rr = (float)(r * r);
        fold(qu[k], mA, mB, (i - r >= 0) ? rr : PINF, bestA, bestB);
        fold(qd[k], mA, mB, (i + r < HH) ? rr : PINF, bestA, bestB);
    }
}

// ---------------------------------------------------------------------------
// Kernel B: column pass, PEEL + GEOMETRIC CHUNKS (fastest measured variant,
// R12: 5.50us). peel r<=2 (1 L2 round-trip) -> ~97% done; chunk r=3..6;
// chunk r=7..14; per-radius residue r>=15. Exact: breaks test the exact
// window condition rbase^2 >= best; extra candidates are valid upper bounds.
// Opposite plane only; 2 px/thread per uint32; fused sqrt epilogue.
// ---------------------------------------------------------------------------
__global__ void __launch_bounds__(256) col_pass(float* __restrict__ out) {
    const int b = blockIdx.x >> 9;           // blockIdx.x = b*512 + i
    const int i = blockIdx.x & 511;
    const int t = threadIdx.x;

    const unsigned int* __restrict__ col =
        reinterpret_cast<const unsigned int*>(g_pack16) +
        (size_t)b * HH * NP + t;

    const unsigned int u   = col[i * NP];
    const unsigned int q1u = col[max(i - 1, 0) * NP];
    const unsigned int q1d = col[min(i + 1, HH - 1) * NP];
    const unsigned int q2u = col[max(i - 2, 0) * NP];
    const unsigned int q2d = col[min(i + 2, HH - 1) * NP];

    const unsigned int mA = (u >> 15) & 1u;
    const unsigned int mB = (u >> 31) & 1u;
    const int roA = (int)(u & 0x7fffu);
    const int roB = (int)((u >> 16) & 0x7fffu);
    float bestA = (float)(roA * roA);
    float bestB = (float)(roB * roB);

    fold(q1u, mA, mB, (i - 1 >= 0) ? 1.0f : PINF, bestA, bestB);
    fold(q1d, mA, mB, (i + 1 < HH) ? 1.0f : PINF, bestA, bestB);
    fold(q2u, mA, mB, (i - 2 >= 0) ? 4.0f : PINF, bestA, bestB);
    fold(q2d, mA, mB, (i + 2 < HH) ? 4.0f : PINF, bestA, bestB);

    if (9.0f < bestA || 9.0f < bestB) {
        chunk<4>(col, i, 3, mA, mB, bestA, bestB);
        if (49.0f < bestA || 49.0f < bestB) {
            chunk<8>(col, i, 7, mA, mB, bestA, bestB);
            #pragma unroll 1
            for (int r = 15; r < HH; ++r) {
                const float rr = (float)(r * r);
                if (rr >= bestA && rr >= bestB) break;
                const int up = i - r, dn = i + r;
                if (up >= 0)  fold(col[up * NP], mA, mB, rr, bestA, bestB);
                if (dn < HH)  fold(col[dn * NP], mA, mB, rr, bestA, bestB);
            }
        }
    }

    float2 o;
    o.x = (mA ? -1.0f : 1.0f) * sqrtf(bestA);
    o.y = (mB ? -1.0f : 1.0f) * sqrtf(bestB);
    reinterpret_cast<float2*>(out + ((size_t)b * HH + i) * WW)[t] = o;
}

extern "C" void kernel_launch(void* const* d_in, const int* in_sizes, int n_in,
                              void* d_out, int out_size) {
    const float* gt = (const float*)d_in[0];
    float* out = (float*)d_out;
    (void)in_sizes; (void)n_in; (void)out_size;

    row_pass<<<BB * HH / 4, 512>>>(gt);
    col_pass<<<BB * HH, 256>>>(out);
}